// round 1
// baseline (speedup 1.0000x reference)
#include <cuda_runtime.h>
#include <cuda_bf16.h>

#define ROWS_T   1048576
#define BINS     17
#define GROUPS   (ROWS_T / 4)      // 262144
#define TPB      64
#define PADSTR   69                // 68 floats per group, padded to odd stride
#define NBLOCKS  (GROUPS / TPB)    // 4096
#define CONVN    33                // 2*17-1

__device__ double g_acc[2];        // [0] = sum KL over rows, [1] = sum weight

__global__ void kd_zero_acc() {
    g_acc[0] = 0.0;
    g_acc[1] = 0.0;
}

__global__ void kd_finalize(float* __restrict__ out) {
    // loss = LOSS_WEIGHT * T^2 * mean(KL) * mean(weight)
    double loss = (g_acc[0] / (double)ROWS_T) * 100.0 * (g_acc[1] / (double)ROWS_T);
    out[0] = (float)loss;
}

// Process one row: returns KL contribution, fills tgt[17] = softmax(raw soft row).
// xs/ys point into conflict-free padded shared memory.
__device__ __forceinline__ float process_row(const float* __restrict__ xs,
                                             const float* __restrict__ ys,
                                             float* __restrict__ tgt) {
    float x[BINS], y[BINS];
#pragma unroll
    for (int j = 0; j < BINS; j++) { x[j] = xs[j]; y[j] = ys[j]; }

    // ---- student (pred) stats ----
    float sx = x[0], mx = x[0];
#pragma unroll
    for (int j = 1; j < BINS; j++) { sx += x[j]; mx = fmaxf(mx, x[j]); }
    float mux = sx * (1.0f / 17.0f);
    float vx = 0.f;
#pragma unroll
    for (int j = 0; j < BINS; j++) { float d = x[j] - mux; vx = fmaf(d, d, vx); }
    float cs  = 1e-7f + sqrtf(vx * (1.0f / 16.0f));
    float isx = __fdividef(0.1f, cs);            // 1/((eps+std)*T)
    float smax = (mx - mux) * isx;
    float Es = 0.f;
#pragma unroll
    for (int j = 0; j < BINS; j++) Es += __expf((x[j] - mux) * isx - smax);
    float lses = smax + __logf(Es);

    // ---- teacher (soft) stats ----
    float sy = y[0], my = y[0];
#pragma unroll
    for (int j = 1; j < BINS; j++) { sy += y[j]; my = fmaxf(my, y[j]); }
    float muy = sy * (1.0f / 17.0f);
    float vy = 0.f;
#pragma unroll
    for (int j = 0; j < BINS; j++) { float d = y[j] - muy; vy = fmaf(d, d, vy); }
    float ct  = 1e-7f + sqrtf(vy * (1.0f / 16.0f));
    float isy = __fdividef(0.1f, ct);
    float tmax = (my - muy) * isy;

    float Et = 0.f, E2 = 0.f, dx = 0.f, dy = 0.f;
#pragma unroll
    for (int j = 0; j < BINS; j++) {
        float e = __expf((y[j] - muy) * isy - tmax);   // unnormalized teacher prob
        Et += e;
        dx = fmaf(e, x[j], dx);
        dy = fmaf(e, y[j], dy);
        float er = __expf(y[j] - my);                  // raw softmax numerator
        E2 += er;
        tgt[j] = er;
    }
    float invE2 = __fdividef(1.f, E2);
#pragma unroll
    for (int j = 0; j < BINS; j++) tgt[j] *= invE2;

    float invEt = __fdividef(1.f, Et);
    float lset = tmax + __logf(Et);

    // KL = sum p*(l_t - l_s)
    //    = (E[y]_p - mu_t)*isy - lse_t - (E[x]_p - mu_s)*isx + lse_s
    float kl = (dy * invEt - muy) * isy - lset
             - (dx * invEt - mux) * isx + lses;
    return kl;
}

__global__ __launch_bounds__(TPB)
void kd_main(const float4* __restrict__ pred4,
             const float4* __restrict__ soft4,
             const float4* __restrict__ w4,
             float* __restrict__ out) {
    __shared__ float sp[TPB * PADSTR];   // pred, padded
    __shared__ float ss[TPB * PADSTR];   // soft, padded (reused as output stage)
    __shared__ float red[4];

    const int tid = threadIdx.x;
    const int blk = blockIdx.x;

    // ---- coalesced copy-in: 1088 float4 per tensor per block (17 per thread) ----
    size_t base4 = (size_t)blk * (TPB * BINS);   // 64 groups * 68 floats / 4 = 1088 float4
#pragma unroll
    for (int k = 0; k < 17; k++) {
        int idx4 = tid + k * TPB;
        float4 a = pred4[base4 + idx4];
        float4 b = soft4[base4 + idx4];
        int i   = idx4 * 4;
        int grp = i / 68;
        int rem = i - grp * 68;       // multiple of 4, <= 64
        int d = grp * PADSTR + rem;
        sp[d] = a.x; sp[d + 1] = a.y; sp[d + 2] = a.z; sp[d + 3] = a.w;
        ss[d] = b.x; ss[d + 1] = b.y; ss[d + 2] = b.z; ss[d + 3] = b.w;
    }
    __syncthreads();

    const float* xs = sp + tid * PADSTR;
    const float* ys = ss + tid * PADSTR;

    float tgt0[BINS], tgt1[BINS];
    float kl = 0.f;

    // rows 0 (top) and 1 (bottom) -> conv_tb
    kl += process_row(xs,      ys,      tgt0);
    kl += process_row(xs + 17, ys + 17, tgt1);

    float tb[CONVN];
#pragma unroll
    for (int k = 0; k < CONVN; k++) tb[k] = 0.f;
#pragma unroll
    for (int i = 0; i < BINS; i++)
#pragma unroll
        for (int j = 0; j < BINS; j++)
            tb[i + j] = fmaf(tgt0[i], tgt1[j], tb[i + j]);

    // rows 2 (left) and 3 (right) -> conv_lr, then ratio
    kl += process_row(xs + 34, ys + 34, tgt0);
    kl += process_row(xs + 51, ys + 51, tgt1);

    float lr[CONVN];
#pragma unroll
    for (int k = 0; k < CONVN; k++) lr[k] = 0.f;
#pragma unroll
    for (int i = 0; i < BINS; i++)
#pragma unroll
        for (int j = 0; j < BINS; j++)
            lr[i + j] = fmaf(tgt0[i], tgt1[j], lr[i + j]);

#pragma unroll
    for (int k = 0; k < CONVN; k++)
        lr[k] = __fdividef(lr[k], tb[k] + 1e-8f);

    // ---- weight sum (coalesced float4) ----
    float4 w = w4[(size_t)blk * TPB + tid];
    float wsum = (w.x + w.y) + (w.z + w.w);

    // ---- output staging: reuse ss as stage buffer (all reads of ss are done after sync) ----
    __syncthreads();
#pragma unroll
    for (int k = 0; k < CONVN; k++)
        ss[tid * CONVN + k] = lr[k];           // stride 33 (odd) -> conflict-free

    // ---- block reduction of KL and weight ----
    float v0 = kl, v1 = wsum;
#pragma unroll
    for (int o = 16; o > 0; o >>= 1) {
        v0 += __shfl_down_sync(0xffffffffu, v0, o);
        v1 += __shfl_down_sync(0xffffffffu, v1, o);
    }
    if ((tid & 31) == 0) {
        red[(tid >> 5) * 2]     = v0;
        red[(tid >> 5) * 2 + 1] = v1;
    }
    __syncthreads();
    if (tid == 0) {
        atomicAdd(&g_acc[0], (double)(red[0] + red[2]));
        atomicAdd(&g_acc[1], (double)(red[1] + red[3]));
    }

    // ---- coalesced output stores: out[1 + group*33 + k] ----
    size_t obase = 1 + (size_t)blk * (TPB * CONVN);
#pragma unroll
    for (int k = 0; k < CONVN; k++) {
        int i = tid + k * TPB;
        out[obase + i] = ss[i];
    }
}

extern "C" void kernel_launch(void* const* d_in, const int* in_sizes, int n_in,
                              void* d_out, int out_size) {
    const float* pred = (const float*)d_in[0];
    const float* soft = (const float*)d_in[1];
    const float* w    = (const float*)d_in[2];
    float* out = (float*)d_out;

    kd_zero_acc<<<1, 1>>>();
    kd_main<<<NBLOCKS, TPB>>>((const float4*)pred, (const float4*)soft,
                              (const float4*)w, out);
    kd_finalize<<<1, 1>>>(out);
}

// round 2
// speedup vs baseline: 1.2583x; 1.2583x over previous
#include <cuda_runtime.h>
#include <cuda_bf16.h>

#define ROWS_T   1048576
#define BINS     17
#define GROUPS   (ROWS_T / 4)      // 262144
#define TPB      128
#define GPB      64                // groups per block (2 threads per group)
#define PADSTR   69                // 68 floats per group, padded to odd stride
#define NBLOCKS  (GROUPS / GPB)    // 4096
#define CONVN    33                // 2*17-1

__device__ float2 g_part[NBLOCKS];   // per-block (sumKL, sumW) — fully overwritten each launch
__device__ int    g_count = 0;       // ticket; last block resets it -> deterministic

// Process one row: returns KL contribution, fills tgt[17] = softmax(raw soft row).
__device__ __forceinline__ float process_row(const float* __restrict__ xs,
                                             const float* __restrict__ ys,
                                             float* __restrict__ tgt) {
    float x[BINS], y[BINS];
#pragma unroll
    for (int j = 0; j < BINS; j++) { x[j] = xs[j]; y[j] = ys[j]; }

    // ---- student (pred) stats ----
    float sx = x[0], mx = x[0];
#pragma unroll
    for (int j = 1; j < BINS; j++) { sx += x[j]; mx = fmaxf(mx, x[j]); }
    float mux = sx * (1.0f / 17.0f);
    float vx = 0.f;
#pragma unroll
    for (int j = 0; j < BINS; j++) { float d = x[j] - mux; vx = fmaf(d, d, vx); }
    float cs  = 1e-7f + sqrtf(vx * (1.0f / 16.0f));
    float isx = __fdividef(0.1f, cs);            // 1/((eps+std)*T)
    float smax = (mx - mux) * isx;
    float Es = 0.f;
#pragma unroll
    for (int j = 0; j < BINS; j++) Es += __expf((x[j] - mux) * isx - smax);
    float lses = smax + __logf(Es);

    // ---- teacher (soft) stats ----
    float sy = y[0], my = y[0];
#pragma unroll
    for (int j = 1; j < BINS; j++) { sy += y[j]; my = fmaxf(my, y[j]); }
    float muy = sy * (1.0f / 17.0f);
    float vy = 0.f;
#pragma unroll
    for (int j = 0; j < BINS; j++) { float d = y[j] - muy; vy = fmaf(d, d, vy); }
    float ct  = 1e-7f + sqrtf(vy * (1.0f / 16.0f));
    float isy = __fdividef(0.1f, ct);
    float tmax = (my - muy) * isy;

    float Et = 0.f, E2 = 0.f, dx = 0.f, dy = 0.f;
#pragma unroll
    for (int j = 0; j < BINS; j++) {
        float e = __expf((y[j] - muy) * isy - tmax);   // unnormalized teacher prob
        Et += e;
        dx = fmaf(e, x[j], dx);
        dy = fmaf(e, y[j], dy);
        float er = __expf(y[j] - my);                  // raw softmax numerator
        E2 += er;
        tgt[j] = er;
    }
    float invE2 = __fdividef(1.f, E2);
#pragma unroll
    for (int j = 0; j < BINS; j++) tgt[j] *= invE2;

    float invEt = __fdividef(1.f, Et);
    float lset = tmax + __logf(Et);

    // KL = (E[y]_p - mu_t)*isy - lse_t - (E[x]_p - mu_s)*isx + lse_s
    return (dy * invEt - muy) * isy - lset
         - (dx * invEt - mux) * isx + lses;
}

__global__ __launch_bounds__(TPB)
void kd_main(const float4* __restrict__ pred4,
             const float4* __restrict__ soft4,
             const float4* __restrict__ w4,
             float* __restrict__ out) {
    __shared__ float sp[GPB * PADSTR];   // pred, padded (reused as output stage)
    __shared__ float ss[GPB * PADSTR];   // soft, padded
    __shared__ float red[8];
    __shared__ double dred[8];
    __shared__ int is_last;

    const int tid = threadIdx.x;
    const int blk = blockIdx.x;

    // ---- coalesced copy-in: 1088 float4 per tensor per block ----
    size_t base4 = (size_t)blk * (GPB * BINS);   // 64 groups * 68 floats / 4 = 1088 float4
#pragma unroll
    for (int k = 0; k < 9; k++) {
        int idx4 = tid + k * TPB;
        if (idx4 < GPB * BINS) {
            float4 a = pred4[base4 + idx4];
            float4 b = soft4[base4 + idx4];
            int i   = idx4 * 4;
            int grp = i / 68;
            int rem = i - grp * 68;       // multiple of 4, <= 64
            int d = grp * PADSTR + rem;
            sp[d] = a.x; sp[d + 1] = a.y; sp[d + 2] = a.z; sp[d + 3] = a.w;
            ss[d] = b.x; ss[d + 1] = b.y; ss[d + 2] = b.z; ss[d + 3] = b.w;
        }
    }
    __syncthreads();

    // 2 threads per group: even lane -> rows 0,1 (tb), odd lane -> rows 2,3 (lr)
    const int g    = tid >> 1;
    const int half = tid & 1;
    const int off  = g * PADSTR + half * 34;

    float tgt0[BINS], tgt1[BINS];
    float kl = process_row(sp + off,      ss + off,      tgt0);
    kl      += process_row(sp + off + 17, ss + off + 17, tgt1);

    float conv[CONVN];
#pragma unroll
    for (int k = 0; k < CONVN; k++) conv[k] = 0.f;
#pragma unroll
    for (int i = 0; i < BINS; i++)
#pragma unroll
        for (int j = 0; j < BINS; j++)
            conv[i + j] = fmaf(tgt0[i], tgt1[j], conv[i + j]);

    // ---- pair exchange: odd lane gets tb from even lane, computes ratio ----
    const int srcLane = tid & 30;   // even lane of this pair (within warp)
    float ratio[CONVN];
#pragma unroll
    for (int k = 0; k < CONVN; k++) {
        float tbk = __shfl_sync(0xffffffffu, conv[k], srcLane);
        ratio[k] = __fdividef(conv[k], tbk + 1e-8f);   // meaningful on odd lanes only
    }

    // ---- weight sum (even lanes only, coalesced float4) ----
    float wsum = 0.f;
    if (!half) {
        float4 w = w4[(size_t)blk * GPB + g];
        wsum = (w.x + w.y) + (w.z + w.w);
    }

    // ---- stage ratio into sp (reuse), conflict-free odd stride 33 ----
    __syncthreads();
    if (half) {
#pragma unroll
        for (int k = 0; k < CONVN; k++)
            sp[g * CONVN + k] = ratio[k];
    }

    // ---- block reduction of KL and weight ----
    float v0 = kl, v1 = wsum;
#pragma unroll
    for (int o = 16; o > 0; o >>= 1) {
        v0 += __shfl_down_sync(0xffffffffu, v0, o);
        v1 += __shfl_down_sync(0xffffffffu, v1, o);
    }
    if ((tid & 31) == 0) {
        red[(tid >> 5) * 2]     = v0;
        red[(tid >> 5) * 2 + 1] = v1;
    }
    __syncthreads();
    if (tid == 0) {
        g_part[blk] = make_float2(red[0] + red[2] + red[4] + red[6],
                                  red[1] + red[3] + red[5] + red[7]);
        __threadfence();
        int t = atomicAdd(&g_count, 1);
        is_last = (t == NBLOCKS - 1);
    }

    // ---- coalesced output stores: out[1 + group*33 + k] ----
    size_t obase = 1 + (size_t)blk * (GPB * CONVN);
#pragma unroll
    for (int k = 0; k < 17; k++) {
        int i = tid + k * TPB;
        if (i < GPB * CONVN) out[obase + i] = sp[i];
    }

    // ---- last block computes the scalar loss ----
    __syncthreads();
    if (is_last) {
        double s0 = 0.0, s1 = 0.0;
        for (int i = tid; i < NBLOCKS; i += TPB) {
            float2 p = g_part[i];
            s0 += (double)p.x; s1 += (double)p.y;
        }
#pragma unroll
        for (int o = 16; o > 0; o >>= 1) {
            s0 += __shfl_down_sync(0xffffffffu, s0, o);
            s1 += __shfl_down_sync(0xffffffffu, s1, o);
        }
        if ((tid & 31) == 0) {
            dred[(tid >> 5) * 2]     = s0;
            dred[(tid >> 5) * 2 + 1] = s1;
        }
        __syncthreads();
        if (tid == 0) {
            double S0 = dred[0] + dred[2] + dred[4] + dred[6];
            double S1 = dred[1] + dred[3] + dred[5] + dred[7];
            // loss = LOSS_WEIGHT * T^2 * mean(KL) * mean(weight)
            out[0] = (float)((S0 / (double)ROWS_T) * 100.0 * (S1 / (double)ROWS_T));
            g_count = 0;   // reset for next (graph-replayed) launch
        }
    }
}

extern "C" void kernel_launch(void* const* d_in, const int* in_sizes, int n_in,
                              void* d_out, int out_size) {
    const float* pred = (const float*)d_in[0];
    const float* soft = (const float*)d_in[1];
    const float* w    = (const float*)d_in[2];
    float* out = (float*)d_out;

    kd_main<<<NBLOCKS, TPB>>>((const float4*)pred, (const float4*)soft,
                              (const float4*)w, out);
}